// round 7
// baseline (speedup 1.0000x reference)
#include <cuda_runtime.h>
#include <cstdint>

// Fused ConvTranspose3d(32->64,k5,s2,p2) + MaxPool2 + MaxPool3 + channel-sum.
// Pools compose into a 6x6x6 stride-6 max over conv output; bias folds after max.
//
// CTA = (n, d2, h2), 320 threads = 10 warps; warp = w2 window, lane = cout pair
// (f32x2, fma.rn.f32x2 = 2 MACs/inst). Full 6x6x6 window per warp (acc 36 u64).
// x patch duplicated-f32x2 in smem (200 KB) -> x reads are LDS.64 broadcasts.
// Weights: prep kernel lays them out per (cin,kh) as contiguous 800-u64 blocks;
// a cp.async 4-deep ring (4 x 6.4 KB) stages one block per (oh,cin,khi) stage,
// 3 in flight. In the mainloop weights are conflict-free LDS.64 into a 25-reg
// cache reused for 195 FFMA2 (7.8 MACs per weight fetch -> L1tex no longer binds).

#define CIN 32
#define COUT 64
#define DI 16
#define HI 32
#define WI 32
#define NTH 320
#define XS_ELEMS 25600                   // 32cin * 5ad * 5ah * 32slots (u64)
#define WSTG_U64 800                     // 25 taps * 32 lanes per stage
#define NBUF 4
#define SMEM_BYTES (XS_ELEMS * 8 + NBUF * WSTG_U64 * 8)   // 204800 + 25600 = 230400

typedef unsigned long long u64;

// [( (cin*5 + kh)*25 + kd*5 + kw )*32 + lane] ; one (cin,kh) block = 800 contiguous u64
__device__ u64 g_wp2[CIN * 5 * 25 * 32];

__global__ void prep_kernel(const float* __restrict__ w) {
    int idx = blockIdx.x * blockDim.x + threadIdx.x;
    if (idx >= CIN * 5 * 25 * 32) return;
    int lane = idx & 31;
    int t = idx >> 5;
    int cin = t / 125;
    int r = t % 125;
    int kh = r / 25;
    int kd = (r % 25) / 5;
    int kw = r % 5;
    int tap = (kd * 5 + kh) * 5 + kw;      // torch tap order (kd,kh,kw)
    unsigned int a = __float_as_uint(w[(cin * COUT + 2 * lane) * 125 + tap]);
    unsigned int b = __float_as_uint(w[(cin * COUT + 2 * lane + 1) * 125 + tap]);
    g_wp2[idx] = ((u64)b << 32) | (u64)a;
}

__device__ __forceinline__ u64 ffma2(u64 a, u64 b, u64 c) {
    u64 d;
    asm("fma.rn.f32x2 %0, %1, %2, %3;" : "=l"(d) : "l"(a), "l"(b), "l"(c));
    return d;
}
__device__ __forceinline__ void unpack2(u64 v, float& lo, float& hi) {
    asm("mov.b64 {%0, %1}, %2;" : "=f"(lo), "=f"(hi) : "l"(v));
}
__device__ __forceinline__ void cp8(unsigned int smem_addr, const u64* g) {
    asm volatile("cp.async.ca.shared.global [%0], [%1], 8;" :: "r"(smem_addr), "l"(g));
}
__device__ __forceinline__ void cp_commit() {
    asm volatile("cp.async.commit_group;");
}
template <int N>
__device__ __forceinline__ void cp_wait() {
    asm volatile("cp.async.wait_group %0;" :: "n"(N));
}

// One (cin,kh) stage: weights from staged smem block, x from broadcast smem.
__device__ __forceinline__ void accum_stage(u64 acc[36],
                                            const u64* __restrict__ xsu,
                                            const u64* __restrict__ wst,
                                            int oh, int kh, int cin,
                                            int w2, int lane) {
    int ah = ((oh + 2 - kh) >> 1) + 1;          // in [0,4]
    u64 wreg[5][5];
#pragma unroll
    for (int kd = 0; kd < 5; kd++)
#pragma unroll
        for (int kw = 0; kw < 5; kw++)
            wreg[kd][kw] = wst[(kd * 5 + kw) * 32 + lane];   // LDS.64, conflict-free

    const u64* xb = xsu + (cin * 25 + ah) * 32 + 3 * w2;
#pragma unroll
    for (int a = 0; a < 5; a++) {
        u64 xp[5];
#pragma unroll
        for (int j = 0; j < 5; j++) xp[j] = xb[a * 160 + j];  // LDS.64 broadcast
#pragma unroll
        for (int kd = 0; kd < 5; kd++) {
            int odl = 2 * a + kd - 4;            // compile-time after unroll
            if (odl < 0 || odl > 5) continue;
#pragma unroll
            for (int kw = 0; kw < 5; kw++) {
                int p = kw & 1;
                int jb = 2 - (kw >> 1);
#pragma unroll
                for (int t3 = 0; t3 < 3; t3++) {
                    int ow = p + 2 * t3;
                    acc[odl * 6 + ow] = ffma2(wreg[kd][kw], xp[jb + t3], acc[odl * 6 + ow]);
                }
            }
        }
    }
}

extern __shared__ u64 smem_dyn[];

struct Cursor { int oh, cin, khi; };

__device__ __forceinline__ void issue_stage(const Cursor& c, int buf,
                                            unsigned int wbase_sa, int tid) {
    if (c.oh < 6) {
        int par = c.oh & 1;
        int kh = par + 2 * c.khi;
        const u64* src = g_wp2 + (c.cin * 5 + kh) * WSTG_U64;
        unsigned int dst = wbase_sa + buf * (WSTG_U64 * 8);
        cp8(dst + tid * 8, src + tid);
        cp8(dst + (tid + 320) * 8, src + tid + 320);
        if (tid < 160) cp8(dst + (tid + 640) * 8, src + tid + 640);
    }
    cp_commit();                                  // empty group past the end is legal
}

__device__ __forceinline__ void advance(Cursor& c) {
    int nkh = (c.oh & 1) ? 2 : 3;
    if (++c.khi == nkh) {
        c.khi = 0;
        if (++c.cin == CIN) { c.cin = 0; c.oh++; }
    }
}

__global__ void __launch_bounds__(NTH, 1)
fused_kernel(const float* __restrict__ x, const float* __restrict__ bias,
             float* __restrict__ out) {
    u64* xsu = smem_dyn;
    u64* wring = smem_dyn + XS_ELEMS;
    unsigned int wbase_sa = (unsigned int)__cvta_generic_to_shared(wring);

    int blk = blockIdx.x;
    int h2 = blk % 10;
    int d2 = (blk / 10) % 5;
    int n = blk / 50;
    int tid = threadIdx.x;

    // ---- prologue: prefetch weight stages 0..2 while x patch loads ----
    Cursor pc{0, 0, 0};
    issue_stage(pc, 0, wbase_sa, tid); advance(pc);
    issue_stage(pc, 1, wbase_sa, tid); advance(pc);
    issue_stage(pc, 2, wbase_sa, tid); advance(pc);

    // ---- load input patch: cin x (id0..id0+4) x (ih0..ih0+4) x (iw=-1..30) ----
    int id0 = 3 * d2 - 1, ih0 = 3 * h2 - 1;
    const float* xbase = x + (size_t)n * CIN * DI * HI * WI;
    for (int i = tid; i < XS_ELEMS; i += NTH) {
        int slot = i & 31;               // iw + 1
        int ah = (i >> 5) % 5;
        int rest = i / 160;
        int ad = rest % 5;
        int cin = rest / 5;
        int iw = slot - 1, id = id0 + ad, ih = ih0 + ah;
        float v = 0.f;
        if (iw >= 0 && id >= 0 && ih >= 0)   // upper bounds always in range for used windows
            v = xbase[((cin * DI + id) * HI + ih) * WI + iw];
        unsigned int u = __float_as_uint(v);
        xsu[i] = ((u64)u << 32) | (u64)u;    // duplicate into both f32x2 halves
    }

    int w2 = tid >> 5;                   // warp id = output w2 window
    int lane = tid & 31;                 // cout pair (2*lane, 2*lane+1)
    float m0 = -3.4e38f, m1 = -3.4e38f;
    int s = 0;                           // stage counter

#pragma unroll 1
    for (int oh = 0; oh < 6; oh++) {
        int par = oh & 1;
        int nkh = par ? 2 : 3;
        u64 acc[36];
#pragma unroll
        for (int i = 0; i < 36; i++) acc[i] = 0ull;

#pragma unroll 1
        for (int cin = 0; cin < CIN; cin++) {
#pragma unroll 1
            for (int khi = 0; khi < nkh; khi++) {
                cp_wait<2>();            // stage s landed (own groups)
                __syncthreads();         // visibility + all warps done with buf (s-1)%4
                issue_stage(pc, (s + 3) & 3, wbase_sa, tid);  // refill freed buffer
                advance(pc);
                int kh = par + 2 * khi;
                accum_stage(acc, xsu, wring + (s & 3) * WSTG_U64, oh, kh, cin, w2, lane);
                s++;
            }
        }

        // fold this oh-plane (6 od x 6 ow) into the running per-channel max
#pragma unroll
        for (int i = 0; i < 36; i++) {
            float lo, hi;
            unpack2(acc[i], lo, hi);
            m0 = fmaxf(m0, lo);
            m1 = fmaxf(m1, hi);
        }
    }

    float b0 = bias[2 * lane], b1 = bias[2 * lane + 1];
    float sm = (m0 + b0) + (m1 + b1);    // bias after max; sum lane's 2 couts
#pragma unroll
    for (int off = 16; off; off >>= 1) sm += __shfl_xor_sync(0xffffffffu, sm, off);
    if (lane == 0) out[((n * 5 + d2) * 10 + h2) * 10 + w2] = sm;
}

extern "C" void kernel_launch(void* const* d_in, const int* in_sizes, int n_in,
                              void* d_out, int out_size) {
    const float* x = (const float*)d_in[0];
    const float* w = (const float*)d_in[1];
    const float* b = (const float*)d_in[2];
    float* out = (float*)d_out;

    static int configured = 0;
    if (!configured) {
        cudaFuncSetAttribute(fused_kernel, cudaFuncAttributeMaxDynamicSharedMemorySize,
                             SMEM_BYTES);
        configured = 1;
    }

    prep_kernel<<<(CIN * 5 * 25 * 32 + 255) / 256, 256>>>(w);
    fused_kernel<<<16 * 5 * 10, NTH, SMEM_BYTES>>>(x, b, out);
}

// round 8
// speedup vs baseline: 1.0133x; 1.0133x over previous
#include <cuda_runtime.h>
#include <cstdint>

// Fused ConvTranspose3d(32->64,k5,s2,p2) + MaxPool2 + MaxPool3 + channel-sum.
// Pools compose into a 6x6x6 stride-6 max over conv output; bias folds after max.
//
// CTA = (n, d2, h2), 320 threads = 10 warps; warp = w2 window, lane = cout pair
// (f32x2 -> 2 MACs per fma.rn.f32x2). Full 6x6x6 window per warp (acc 36 u64).
// x patch cin x 5 x 5 x 32 stored as plain float (100 KB smem); x reads are
// LDS.32 broadcast + mov-dup. Weights pre-flattened per stage into g_wflat
// (3 MB, L2-resident) and streamed through a double-buffered 8-stage cp.async
// ring (2 x 51.2 KB). Mainloop: 25 conflict-free LDS.64 fill wreg[5][5], reused
// for 225 FFMA2 -> ~71% fma issue mix with only LDS-level latency to hide.

#define CIN 32
#define COUT 64
#define DI 16
#define HI 32
#define WI 32
#define NTH 320
#define XS_ELEMS 25600                   // floats: 32cin * 5ad * 5ah * 32slots
#define STG_U64 800                      // 25 taps * 32 lanes per stage
#define GSTG 8                           // stages per group
#define GRP_U64 (STG_U64 * GSTG)         // 6400 u64 per group
#define NGRP 60                          // 480 stages total
#define SMEM_BYTES (XS_ELEMS * 4 + 2 * GRP_U64 * 8)   // 102400 + 102400 = 204800

typedef unsigned long long u64;

// Flattened weight stream: stage t = 0..479 in (oh-major, cin, khi) order,
// within stage: (kd*5+kw)*32 + lane, pair-packed (lo=cout 2*lane, hi=2*lane+1).
__device__ u64 g_wflat[480 * STG_U64];

__global__ void prep_kernel(const float* __restrict__ w) {
    int idx = blockIdx.x * blockDim.x + threadIdx.x;
    if (idx >= 480 * STG_U64) return;
    int r = idx % STG_U64;
    int t = idx / STG_U64;
    int lane = r & 31;
    int kdkw = r >> 5;
    int kd = kdkw / 5, kw = kdkw % 5;
    // stage t -> oh, cin, khi  (oh sizes: even 96, odd 64, pair = 160)
    int blkp = t / 160, rem = t % 160;
    int odd = (rem >= 96);
    int oh = 2 * blkp + odd;
    int s = odd ? rem - 96 : rem;
    int nkh = odd ? 2 : 3;
    int cin = s / nkh, khi = s % nkh;
    int kh = (oh & 1) + 2 * khi;
    int tap = (kd * 5 + kh) * 5 + kw;      // torch tap order (kd,kh,kw)
    unsigned int a = __float_as_uint(w[(cin * COUT + 2 * lane) * 125 + tap]);
    unsigned int b = __float_as_uint(w[(cin * COUT + 2 * lane + 1) * 125 + tap]);
    g_wflat[idx] = ((u64)b << 32) | (u64)a;
}

__device__ __forceinline__ u64 ffma2(u64 a, u64 b, u64 c) {
    u64 d;
    asm("fma.rn.f32x2 %0, %1, %2, %3;" : "=l"(d) : "l"(a), "l"(b), "l"(c));
    return d;
}
__device__ __forceinline__ void unpack2(u64 v, float& lo, float& hi) {
    asm("mov.b64 {%0, %1}, %2;" : "=f"(lo), "=f"(hi) : "l"(v));
}
__device__ __forceinline__ u64 lddup(const float* p) {   // LDS.32 + dup to f32x2
    float f = *p;
    u64 d;
    asm("mov.b64 %0, {%1, %1};" : "=l"(d) : "f"(f));
    return d;
}
__device__ __forceinline__ void cp16(unsigned int sa, const u64* g) {
    asm volatile("cp.async.cg.shared.global [%0], [%1], 16;" :: "r"(sa), "l"(g));
}
__device__ __forceinline__ void cp_commit() { asm volatile("cp.async.commit_group;"); }
template <int N>
__device__ __forceinline__ void cp_wait() {
    asm volatile("cp.async.wait_group %0;" :: "n"(N));
}

// Copy group g (6400 u64, contiguous) into ring buffer g&1. 20 u64 per thread.
__device__ __forceinline__ void issue_group(int g, unsigned int wbase_sa, int tid) {
    if (g < NGRP) {
        const u64* src = g_wflat + (size_t)g * GRP_U64 + tid * 20;
        unsigned int dst = wbase_sa + (unsigned)(g & 1) * (GRP_U64 * 8) + tid * 160;
#pragma unroll
        for (int k = 0; k < 10; k++) cp16(dst + k * 16, src + 2 * k);
    }
    cp_commit();                         // empty group past the end keeps counts aligned
}

// Compute one 8-stage group for this warp's (w2) window / lane's cout pair.
template <int NKH>
__device__ __forceinline__ void compute_group(u64 acc[36],
                                              const float* __restrict__ xs,
                                              const u64* __restrict__ wbuf,
                                              int oh, int gi, int w2, int lane) {
#pragma unroll 1
    for (int j = 0; j < GSTG; j++) {
        int s = gi * GSTG + j;
        int cin = s / NKH, khi = s % NKH;
        int kh = (oh & 1) + 2 * khi;
        int ah = ((oh + 2 - kh) >> 1) + 1;            // in [0,4]

        const u64* wst = wbuf + j * STG_U64;
        u64 wreg[5][5];
#pragma unroll
        for (int kd = 0; kd < 5; kd++)
#pragma unroll
            for (int kw = 0; kw < 5; kw++)
                wreg[kd][kw] = wst[(kd * 5 + kw) * 32 + lane];   // LDS.64 conflict-free

        const float* xb = xs + (cin * 25 + ah) * 32 + 3 * w2;
#pragma unroll
        for (int a = 0; a < 5; a++) {
            u64 xp[5];
#pragma unroll
            for (int q = 0; q < 5; q++) xp[q] = lddup(xb + a * 160 + q);
#pragma unroll
            for (int kd = 0; kd < 5; kd++) {
                int odl = 2 * a + kd - 4;             // compile-time after unroll
                if (odl < 0 || odl > 5) continue;
#pragma unroll
                for (int kw = 0; kw < 5; kw++) {
                    int p = kw & 1;
                    int jb = 2 - (kw >> 1);
#pragma unroll
                    for (int t3 = 0; t3 < 3; t3++) {
                        int ow = p + 2 * t3;
                        acc[odl * 6 + ow] =
                            ffma2(wreg[kd][kw], xp[jb + t3], acc[odl * 6 + ow]);
                    }
                }
            }
        }
    }
}

extern __shared__ float smem_dyn[];

__global__ void __launch_bounds__(NTH, 1)
fused_kernel(const float* __restrict__ x, const float* __restrict__ bias,
             float* __restrict__ out) {
    float* xs = smem_dyn;                                   // 25600 floats
    u64* wring = (u64*)(smem_dyn + XS_ELEMS);               // 2 x 6400 u64
    unsigned int wbase_sa = (unsigned int)__cvta_generic_to_shared(wring);

    int blk = blockIdx.x;
    int h2 = blk % 10;
    int d2 = (blk / 10) % 5;
    int n = blk / 50;
    int tid = threadIdx.x;

    // ---- prologue: prefetch weight groups 0,1 while x patch loads ----
    issue_group(0, wbase_sa, tid);
    issue_group(1, wbase_sa, tid);

    // ---- load input patch: cin x (id0..id0+4) x (ih0..ih0+4) x (iw=-1..30) ----
    int id0 = 3 * d2 - 1, ih0 = 3 * h2 - 1;
    const float* xbase = x + (size_t)n * CIN * DI * HI * WI;
    for (int i = tid; i < XS_ELEMS; i += NTH) {
        int slot = i & 31;               // iw + 1
        int ah = (i >> 5) % 5;
        int rest = i / 160;
        int ad = rest % 5;
        int cin = rest / 5;
        int iw = slot - 1, id = id0 + ad, ih = ih0 + ah;
        float v = 0.f;
        if (iw >= 0 && id >= 0 && ih >= 0)   // upper bounds always in range for used windows
            v = xbase[((cin * DI + id) * HI + ih) * WI + iw];
        xs[i] = v;
    }

    int w2 = tid >> 5;                   // warp id = output w2 window
    int lane = tid & 31;                 // cout pair (2*lane, 2*lane+1)
    float m0 = -3.4e38f, m1 = -3.4e38f;
    int g = 0;                           // global group counter

#pragma unroll 1
    for (int oh = 0; oh < 6; oh++) {
        int par = oh & 1;
        int ngi = par ? 8 : 12;          // groups in this oh (64 or 96 stages)
        u64 acc[36];
#pragma unroll
        for (int i = 0; i < 36; i++) acc[i] = 0ull;

#pragma unroll 1
        for (int gi = 0; gi < ngi; gi++) {
            cp_wait<1>();                // group g landed (g+1 may be in flight)
            __syncthreads();             // visibility (and xs ready on first iter)
            const u64* wbuf = wring + (g & 1) * GRP_U64;
            if (par) compute_group<2>(acc, xs, wbuf, oh, gi, w2, lane);
            else     compute_group<3>(acc, xs, wbuf, oh, gi, w2, lane);
            __syncthreads();             // all warps done reading buffer g&1
            issue_group(g + 2, wbase_sa, tid);
            g++;
        }

        // fold this oh-plane (6 od x 6 ow) into the running per-channel max
#pragma unroll
        for (int i = 0; i < 36; i++) {
            float lo, hi;
            unpack2(acc[i], lo, hi);
            m0 = fmaxf(m0, lo);
            m1 = fmaxf(m1, hi);
        }
    }

    float b0 = bias[2 * lane], b1 = bias[2 * lane + 1];
    float sm = (m0 + b0) + (m1 + b1);    // bias after max; sum lane's 2 couts
#pragma unroll
    for (int off = 16; off; off >>= 1) sm += __shfl_xor_sync(0xffffffffu, sm, off);
    if (lane == 0) out[((n * 5 + d2) * 10 + h2) * 10 + w2] = sm;
}

extern "C" void kernel_launch(void* const* d_in, const int* in_sizes, int n_in,
                              void* d_out, int out_size) {
    const float* x = (const float*)d_in[0];
    const float* w = (const float*)d_in[1];
    const float* b = (const float*)d_in[2];
    float* out = (float*)d_out;

    static int configured = 0;
    if (!configured) {
        cudaFuncSetAttribute(fused_kernel, cudaFuncAttributeMaxDynamicSharedMemorySize,
                             SMEM_BYTES);
        configured = 1;
    }

    prep_kernel<<<(480 * STG_U64 + 255) / 256, 256>>>(w);
    fused_kernel<<<16 * 5 * 10, NTH, SMEM_BYTES>>>(x, b, out);
}

// round 11
// speedup vs baseline: 1.1433x; 1.1284x over previous
#include <cuda_runtime.h>
#include <cstdint>

// Fused ConvTranspose3d(32->64,k5,s2,p2) + MaxPool2 + MaxPool3 + channel-sum.
// Pools compose into a 6x6x6 stride-6 max over conv output; bias folds after max.
//
// CTA = (n, d2, h2), 640 threads = 20 warps = (w2 in 0..9) x (ow-PARITY p).
// Stride-2 transpose conv => parity(ow) == parity(kw): the parity split is an
// exact partition of both the FFMA work AND the weight reads (no duplication).
// lane = cout pair (f32x2 -> 2 MACs / fma.rn.f32x2). acc = 6 od x 3 ow = 18 u64.
// x patch (cin x 5 x 5 x 32 floats, 100 KB smem) read as LDS.32 broadcast + dup.
// Weights flattened per stage (parity-ordered taps) in g_wflat (L2-resident),
// streamed via a double-buffered 8-stage cp.async ring (2 x 51.2 KB).

#define CIN 32
#define COUT 64
#define DI 16
#define HI 32
#define WI 32
#define NTH 640
#define XS_ELEMS 25600                   // floats: 32cin * 5ad * 5ah * 32slots
#define STG_U64 800                      // 25 taps * 32 lanes (even-kw first 480, odd 320)
#define GSTG 8
#define GRP_U64 (STG_U64 * GSTG)         // 6400
#define NGRP 60                          // 480 stages
#define SMEM_BYTES (XS_ELEMS * 4 + 2 * GRP_U64 * 8)   // 102400 + 102400 = 204800

typedef unsigned long long u64;

// Stage t = (oh-major, cin, khi); within stage: even kw taps at r=(kd*3+kwi)*32+lane,
// odd kw taps at 480+(kd*2+kwi)*32+lane. Pair-packed couts (lo=2*lane, hi=2*lane+1).
__device__ u64 g_wflat[480 * STG_U64];

__global__ void prep_kernel(const float* __restrict__ w) {
    int idx = blockIdx.x * blockDim.x + threadIdx.x;
    if (idx >= 480 * STG_U64) return;
    int r = idx % STG_U64;
    int t = idx / STG_U64;
    int lane = r & 31;
    int kd, kw;
    if (r < 480) { int q = r >> 5; kd = q / 3; kw = 2 * (q % 3); }
    else         { int q = (r - 480) >> 5; kd = q / 2; kw = 2 * (q % 2) + 1; }
    // stage t -> oh, cin, khi  (even oh: 96 stages, odd: 64; pair = 160)
    int blkp = t / 160, rem = t % 160;
    int odd = (rem >= 96);
    int oh = 2 * blkp + odd;
    int s = odd ? rem - 96 : rem;
    int nkh = odd ? 2 : 3;
    int cin = s / nkh, khi = s % nkh;
    int kh = (oh & 1) + 2 * khi;
    int tap = (kd * 5 + kh) * 5 + kw;      // torch tap order (kd,kh,kw)
    unsigned int a = __float_as_uint(w[(cin * COUT + 2 * lane) * 125 + tap]);
    unsigned int b = __float_as_uint(w[(cin * COUT + 2 * lane + 1) * 125 + tap]);
    g_wflat[idx] = ((u64)b << 32) | (u64)a;
}

__device__ __forceinline__ u64 ffma2(u64 a, u64 b, u64 c) {
    u64 d;
    asm("fma.rn.f32x2 %0, %1, %2, %3;" : "=l"(d) : "l"(a), "l"(b), "l"(c));
    return d;
}
__device__ __forceinline__ void unpack2(u64 v, float& lo, float& hi) {
    asm("mov.b64 {%0, %1}, %2;" : "=f"(lo), "=f"(hi) : "l"(v));
}
__device__ __forceinline__ u64 lddup(const float* p) {   // LDS.32 bcast + dup
    float f = *p;
    u64 d;
    asm("mov.b64 %0, {%1, %1};" : "=l"(d) : "f"(f));
    return d;
}
__device__ __forceinline__ void cp16(unsigned int sa, const u64* g) {
    asm volatile("cp.async.cg.shared.global [%0], [%1], 16;" :: "r"(sa), "l"(g));
}
__device__ __forceinline__ void cp_commit() { asm volatile("cp.async.commit_group;"); }
template <int N>
__device__ __forceinline__ void cp_wait() {
    asm volatile("cp.async.wait_group %0;" :: "n"(N));
}

// Copy group g (6400 u64) into ring half g&1. 640 threads -> 10 u64 each.
__device__ __forceinline__ void issue_group(int g, unsigned int wbase_sa, int tid) {
    if (g < NGRP) {
        const u64* src = g_wflat + (size_t)g * GRP_U64 + tid * 10;
        unsigned int dst = wbase_sa + (unsigned)(g & 1) * (GRP_U64 * 8) + tid * 80;
#pragma unroll
        for (int k = 0; k < 5; k++) cp16(dst + k * 16, src + 2 * k);
    }
    cp_commit();                          // empty trailing groups keep counts aligned
}

// One 8-stage group for this warp's parity P of window w2. NW = taps per kd row.
template <int NKH, int P>
__device__ __forceinline__ void compute_group(u64 acc[18],
                                              const float* __restrict__ xs,
                                              const u64* __restrict__ wbuf,
                                              int oh, int gi, int w2, int lane) {
    constexpr int NW = P ? 2 : 3;         // kw = 2*kwi + P
#pragma unroll 1
    for (int j = 0; j < GSTG; j++) {
        int s = gi * GSTG + j;
        int cin = s / NKH, khi = s % NKH;
        int kh = (oh & 1) + 2 * khi;
        int ah = ((oh + 2 - kh) >> 1) + 1;            // in [0,4]

        const u64* wst = wbuf + j * STG_U64 + (P ? 480 : 0);
        u64 wreg[5][NW];
#pragma unroll
        for (int kd = 0; kd < 5; kd++)
#pragma unroll
            for (int kwi = 0; kwi < NW; kwi++)
                wreg[kd][kwi] = wst[(kd * NW + kwi) * 32 + lane];  // LDS.64 conflict-free

        const float* xb = xs + (cin * 25 + ah) * 32 + 3 * w2;
#pragma unroll
        for (int a = 0; a < 5; a++) {
            u64 xp[5];
#pragma unroll
            for (int q = P; q < 5; q++) xp[q] = lddup(xb + a * 160 + q);
#pragma unroll
            for (int kd = 0; kd < 5; kd++) {
                int odl = 2 * a + kd - 4;             // compile-time after unroll
                if (odl < 0 || odl > 5) continue;
#pragma unroll
                for (int kwi = 0; kwi < NW; kwi++) {
#pragma unroll
                    for (int t3 = 0; t3 < 3; t3++) {   // ow = P + 2*t3
                        acc[odl * 3 + t3] =
                            ffma2(wreg[kd][kwi], xp[2 - kwi + t3], acc[odl * 3 + t3]);
                    }
                }
            }
        }
    }
}

extern __shared__ float smem_dyn[];

__global__ void __launch_bounds__(NTH, 1)
fused_kernel(const float* __restrict__ x, const float* __restrict__ bias,
             float* __restrict__ out) {
    float* xs = smem_dyn;                                   // 25600 floats
    u64* wring = (u64*)(smem_dyn + XS_ELEMS);               // 2 x 6400 u64
    unsigned int wbase_sa = (unsigned int)__cvta_generic_to_shared(wring);

    int blk = blockIdx.x;
    int h2 = blk % 10;
    int d2 = (blk / 10) % 5;
    int n = blk / 50;
    int tid = threadIdx.x;

    // ---- prologue: prefetch weight groups 0,1 while x patch loads ----
    issue_group(0, wbase_sa, tid);
    issue_group(1, wbase_sa, tid);

    // ---- load input patch: cin x (id0..id0+4) x (ih0..ih0+4) x (iw=-1..30) ----
    int id0 = 3 * d2 - 1, ih0 = 3 * h2 - 1;
    const float* xbase = x + (size_t)n * CIN * DI * HI * WI;
    for (int i = tid; i < XS_ELEMS; i += NTH) {
        int slot = i & 31;               // iw + 1
        int ah = (i >> 5) % 5;
        int rest = i / 160;
        int ad = rest % 5;
        int cin = rest / 5;
        int iw = slot - 1, id = id0 + ad, ih = ih0 + ah;
        float v = 0.f;
        if (iw >= 0 && id >= 0 && ih >= 0)   // upper bounds always in range for used windows
            v = xbase[((cin * DI + id) * HI + ih) * WI + iw];
        xs[i] = v;
    }

    int wid = tid >> 5;
    int w2 = wid % 10;                   // output w2 window
    int p = wid / 10;                    // ow parity handled by this warp
    int lane = tid & 31;                 // cout pair (2*lane, 2*lane+1)
    float m0 = -3.4e38f, m1 = -3.4e38f;
    int g = 0;

#pragma unroll 1
    for (int oh = 0; oh < 6; oh++) {
        int par = oh & 1;
        int ngi = par ? 8 : 12;          // groups in this oh (64 / 96 stages)
        u64 acc[18];
#pragma unroll
        for (int i = 0; i < 18; i++) acc[i] = 0ull;

#pragma unroll 1
        for (int gi = 0; gi < ngi; gi++) {
            cp_wait<1>();                // group g landed (g+1 may be in flight)
            __syncthreads();             // visibility (and xs ready on first iter)
            const u64* wbuf = wring + (g & 1) * GRP_U64;
            if (p == 0) {
                if (par) compute_group<2, 0>(acc, xs, wbuf, oh, gi, w2, lane);
                else     compute_group<3, 0>(acc, xs, wbuf, oh, gi, w2, lane);
            } else {
                if (par) compute_group<2, 1>(acc, xs, wbuf, oh, gi, w2, lane);
                else     compute_group<3, 1>(acc, xs, wbuf, oh, gi, w2, lane);
            }
            __syncthreads();             // all warps done reading ring half g&1
            issue_group(g + 2, wbase_sa, tid);
            g++;
        }

        // fold this oh-plane slice (6 od x 3 ow of this parity) into running max
#pragma unroll
        for (int i = 0; i < 18; i++) {
            float lo, hi;
            unpack2(acc[i], lo, hi);
            m0 = fmaxf(m0, lo);
            m1 = fmaxf(m1, hi);
        }
    }

    // ---- merge ow parities (x patch dead -> reuse smem), bias, channel sum ----
    __syncthreads();
    float* red = smem_dyn;
    if (p == 1) {
        red[(w2 * 32 + lane) * 2 + 0] = m0;
        red[(w2 * 32 + lane) * 2 + 1] = m1;
    }
    __syncthreads();
    if (p == 0) {
        m0 = fmaxf(m0, red[(w2 * 32 + lane) * 2 + 0]);
        m1 = fmaxf(m1, red[(w2 * 32 + lane) * 2 + 1]);
        float b0 = bias[2 * lane], b1 = bias[2 * lane + 1];
        float sm = (m0 + b0) + (m1 + b1);    // bias after max; sum lane's 2 couts
#pragma unroll
        for (int off = 16; off; off >>= 1) sm += __shfl_xor_sync(0xffffffffu, sm, off);
        if (lane == 0) out[((n * 5 + d2) * 10 + h2) * 10 + w2] = sm;
    }
}

extern "C" void kernel_launch(void* const* d_in, const int* in_sizes, int n_in,
                              void* d_out, int out_size) {
    const float* x = (const float*)d_in[0];
    const float* w = (const float*)d_in[1];
    const float* b = (const float*)d_in[2];
    float* out = (float*)d_out;

    static int configured = 0;
    if (!configured) {
        cudaFuncSetAttribute(fused_kernel, cudaFuncAttributeMaxDynamicSharedMemorySize,
                             SMEM_BYTES);
        configured = 1;
    }

    prep_kernel<<<(480 * STG_U64 + 255) / 256, 256>>>(w);
    fused_kernel<<<16 * 5 * 10, NTH, SMEM_BYTES>>>(x, b, out);
}

// round 12
// speedup vs baseline: 1.2890x; 1.1274x over previous
#include <cuda_runtime.h>
#include <cstdint>

// Fused ConvTranspose3d(32->64,k5,s2,p2) + MaxPool2 + MaxPool3 + channel-sum.
// Pools compose into a 6x6x6 stride-6 max over conv output; bias folds after max.
//
// CTA = (n, d2, h2), 640 threads = 20 warps = (w2 in 0..9) x (ow-PARITY p).
// Stride-2 transpose conv => parity(ow) == parity(kw): parity split exactly
// partitions FFMA work AND weight reads. lane = cout pair (f32x2 = 2 MACs/inst).
// acc = 6 od x 3 ow = 18 u64. x patch stored DUPLICATED-f32x2 (200 KB smem) so
// each x read is ONE broadcast LDS.64 (no mov-dup). Weights pair-packed in g_wp
// (L2-resident, 6.4 KB per (cin,kh) stage shared by all warps) read with
// coalesced per-lane LDG.64 — NO barriers in the mainloop, warps drift freely.
// Per-P0-warp stage mix: 135 FFMA2 vs ~52 other issues (~72% FFMA2).

#define CIN 32
#define COUT 64
#define DI 16
#define HI 32
#define WI 32
#define NTH 640
#define XS_ELEMS 25600                   // u64: 32cin * 5ad * 5ah * 32slots
#define SMEM_BYTES (XS_ELEMS * 8)        // 200 KB

typedef unsigned long long u64;

// Per (cin,kh) block of 800 u64: even-kw taps at (kd*3+kwi)*32+lane (r<480),
// odd-kw taps at 480+(kd*2+kwi)*32+lane. Pair-packed couts (lo=2*lane, hi=2*lane+1).
__device__ u64 g_wp[CIN * 5 * 800];

__global__ void prep_kernel(const float* __restrict__ w) {
    int idx = blockIdx.x * blockDim.x + threadIdx.x;
    if (idx >= CIN * 5 * 800) return;
    int r = idx % 800;
    int blkid = idx / 800;
    int cin = blkid / 5, kh = blkid % 5;
    int lane = r & 31;
    int kd, kw;
    if (r < 480) { int q = r >> 5; kd = q / 3; kw = 2 * (q % 3); }
    else         { int q = (r - 480) >> 5; kd = q / 2; kw = 2 * (q % 2) + 1; }
    int tap = (kd * 5 + kh) * 5 + kw;      // torch tap order (kd,kh,kw)
    unsigned int a = __float_as_uint(w[(cin * COUT + 2 * lane) * 125 + tap]);
    unsigned int b = __float_as_uint(w[(cin * COUT + 2 * lane + 1) * 125 + tap]);
    g_wp[idx] = ((u64)b << 32) | (u64)a;
}

__device__ __forceinline__ u64 ffma2(u64 a, u64 b, u64 c) {
    u64 d;
    asm("fma.rn.f32x2 %0, %1, %2, %3;" : "=l"(d) : "l"(a), "l"(b), "l"(c));
    return d;
}
__device__ __forceinline__ void unpack2(u64 v, float& lo, float& hi) {
    asm("mov.b64 {%0, %1}, %2;" : "=f"(lo), "=f"(hi) : "l"(v));
}

// One (oh,cin,kh) stage for this warp's parity P of window w2.
template <int P>
__device__ __forceinline__ void accum_stage(u64 acc[18],
                                            const u64* __restrict__ xsu,
                                            int oh, int kh, int cin,
                                            int w2, int lane) {
    constexpr int NW = P ? 2 : 3;         // kw = 2*kwi + P
    int ah = ((oh + 2 - kh) >> 1) + 1;    // in [0,4]

    const u64* wbase = g_wp + (cin * 5 + kh) * 800 + (P ? 480 : 0) + lane;
    u64 wreg[5][NW];
#pragma unroll
    for (int kd = 0; kd < 5; kd++)
#pragma unroll
        for (int kwi = 0; kwi < NW; kwi++)
            wreg[kd][kwi] = __ldg(wbase + (kd * NW + kwi) * 32);  // coalesced LDG.64

    const u64* xb = xsu + (cin * 25 + ah) * 32 + 3 * w2;
#pragma unroll
    for (int a = 0; a < 5; a++) {
        u64 xp[5];
#pragma unroll
        for (int q = P; q < 5; q++) xp[q] = xb[a * 160 + q];      // broadcast LDS.64
#pragma unroll
        for (int kd = 0; kd < 5; kd++) {
            int odl = 2 * a + kd - 4;      // compile-time after unroll
            if (odl < 0 || odl > 5) continue;
#pragma unroll
            for (int kwi = 0; kwi < NW; kwi++) {
#pragma unroll
                for (int t3 = 0; t3 < 3; t3++) {   // ow = P + 2*t3
                    acc[odl * 3 + t3] =
                        ffma2(wreg[kd][kwi], xp[2 - kwi + t3], acc[odl * 3 + t3]);
                }
            }
        }
    }
}

extern __shared__ u64 smem_dyn[];

__global__ void __launch_bounds__(NTH, 1)
fused_kernel(const float* __restrict__ x, const float* __restrict__ bias,
             float* __restrict__ out) {
    u64* xsu = smem_dyn;                  // 25600 u64, duplicated f32x2

    int blk = blockIdx.x;
    int h2 = blk % 10;
    int d2 = (blk / 10) % 5;
    int n = blk / 50;
    int tid = threadIdx.x;

    // ---- load input patch: cin x (id0..id0+4) x (ih0..ih0+4) x (iw=-1..30) ----
    int id0 = 3 * d2 - 1, ih0 = 3 * h2 - 1;
    const float* xbase = x + (size_t)n * CIN * DI * HI * WI;
    for (int i = tid; i < XS_ELEMS; i += NTH) {
        int slot = i & 31;               // iw + 1
        int ah = (i >> 5) % 5;
        int rest = i / 160;
        int ad = rest % 5;
        int cin = rest / 5;
        int iw = slot - 1, id = id0 + ad, ih = ih0 + ah;
        float v = 0.f;
        if (iw >= 0 && id >= 0 && ih >= 0)   // upper bounds always in range for used windows
            v = xbase[((cin * DI + id) * HI + ih) * WI + iw];
        unsigned int u = __float_as_uint(v);
        xsu[i] = ((u64)u << 32) | (u64)u;    // duplicate into both f32x2 halves
    }
    __syncthreads();

    int wid = tid >> 5;
    int w2 = wid % 10;                   // output w2 window
    int p = wid / 10;                    // ow parity handled by this warp
    int lane = tid & 31;                 // cout pair (2*lane, 2*lane+1)
    float m0 = -3.4e38f, m1 = -3.4e38f;

#pragma unroll 1
    for (int oh = 0; oh < 6; oh++) {
        int par = oh & 1;
        int nkh = par ? 2 : 3;
        u64 acc[18];
#pragma unroll
        for (int i = 0; i < 18; i++) acc[i] = 0ull;

#pragma unroll 1
        for (int cin = 0; cin < CIN; cin++) {
#pragma unroll 1
            for (int khi = 0; khi < nkh; khi++) {
                int kh = par + 2 * khi;
                if (p == 0) accum_stage<0>(acc, xsu, oh, kh, cin, w2, lane);
                else        accum_stage<1>(acc, xsu, oh, kh, cin, w2, lane);
            }
        }

        // fold this oh-plane slice (6 od x 3 ow of this parity) into running max
#pragma unroll
        for (int i = 0; i < 18; i++) {
            float lo, hi;
            unpack2(acc[i], lo, hi);
            m0 = fmaxf(m0, lo);
            m1 = fmaxf(m1, hi);
        }
    }

    // ---- merge ow parities (x patch dead -> reuse smem), bias, channel sum ----
    __syncthreads();
    float* red = (float*)smem_dyn;
    if (p == 1) {
        red[(w2 * 32 + lane) * 2 + 0] = m0;
        red[(w2 * 32 + lane) * 2 + 1] = m1;
    }
    __syncthreads();
    if (p == 0) {
        m0 = fmaxf(m0, red[(w2 * 32 + lane) * 2 + 0]);
        m1 = fmaxf(m1, red[(w2 * 32 + lane) * 2 + 1]);
        float b0 = bias[2 * lane], b1 = bias[2 * lane + 1];
        float sm = (m0 + b0) + (m1 + b1);    // bias after max; sum lane's 2 couts
#pragma unroll
        for (int off = 16; off; off >>= 1) sm += __shfl_xor_sync(0xffffffffu, sm, off);
        if (lane == 0) out[((n * 5 + d2) * 10 + h2) * 10 + w2] = sm;
    }
}

extern "C" void kernel_launch(void* const* d_in, const int* in_sizes, int n_in,
                              void* d_out, int out_size) {
    const float* x = (const float*)d_in[0];
    const float* w = (const float*)d_in[1];
    const float* b = (const float*)d_in[2];
    float* out = (float*)d_out;

    static int configured = 0;
    if (!configured) {
        cudaFuncSetAttribute(fused_kernel, cudaFuncAttributeMaxDynamicSharedMemorySize,
                             SMEM_BYTES);
        configured = 1;
    }

    prep_kernel<<<(CIN * 5 * 800 + 255) / 256, 256>>>(w);
    fused_kernel<<<16 * 5 * 10, NTH, SMEM_BYTES>>>(x, b, out);
}

// round 15
// speedup vs baseline: 1.3173x; 1.0220x over previous
#include <cuda_runtime.h>
#include <cstdint>

// Fused ConvTranspose3d(32->64,k5,s2,p2) + MaxPool2 + MaxPool3 + channel-sum.
// Pools compose into a 6x6x6 stride-6 max over conv output; bias folds after max.
//
// CTA = (n, d2, h2), 640 threads = 20 warps = (w2 in 0..9) x (ow-PARITY P).
// parity(ow) == parity(kw) exactly partitions FFMA work and weight reads.
// lane = cout pair (f32x2 -> 2 MACs per fma.rn.f32x2). acc = 6 od x 3 ow = 18 u64.
// x patch DUPLICATED-f32x2 (200 KB smem): consecutive slots are adjacent u64s, so
// x reads are 16B-aligned broadcast LDS.128 (ulonglong2); alignment parity
// E = w2&1 is a template param. Weights pair-packed in g_wp (L2-resident),
// coalesced per-lane LDG.64, no mainloop barriers; khi fully unrolled so ptxas
// can overlap next-stage weight loads with current FFMA block.

#define CIN 32
#define COUT 64
#define DI 16
#define HI 32
#define WI 32
#define NTH 640
#define XS_ELEMS 25600                   // u64: 32cin * 5ad * 5ah * 32slots
#define SMEM_BYTES (XS_ELEMS * 8)        // 200 KB

typedef unsigned long long u64;

// Per (cin,kh) block of 800 u64: even-kw taps at (kd*3+kwi)*32+lane (r<480),
// odd-kw taps at 480+(kd*2+kwi)*32+lane. Pair-packed couts (lo=2*lane, hi=2*lane+1).
__device__ u64 g_wp[CIN * 5 * 800];

__global__ void prep_kernel(const float* __restrict__ w) {
    int idx = blockIdx.x * blockDim.x + threadIdx.x;
    if (idx >= CIN * 5 * 800) return;
    int r = idx % 800;
    int blkid = idx / 800;
    int cin = blkid / 5, kh = blkid % 5;
    int lane = r & 31;
    int kd, kw;
    if (r < 480) { int q = r >> 5; kd = q / 3; kw = 2 * (q % 3); }
    else         { int q = (r - 480) >> 5; kd = q / 2; kw = 2 * (q % 2) + 1; }
    int tap = (kd * 5 + kh) * 5 + kw;      // torch tap order (kd,kh,kw)
    unsigned int a = __float_as_uint(w[(cin * COUT + 2 * lane) * 125 + tap]);
    unsigned int b = __float_as_uint(w[(cin * COUT + 2 * lane + 1) * 125 + tap]);
    g_wp[idx] = ((u64)b << 32) | (u64)a;
}

__device__ __forceinline__ u64 ffma2(u64 a, u64 b, u64 c) {
    u64 d;
    asm("fma.rn.f32x2 %0, %1, %2, %3;" : "=l"(d) : "l"(a), "l"(b), "l"(c));
    return d;
}
__device__ __forceinline__ void unpack2(u64 v, float& lo, float& hi) {
    asm("mov.b64 {%0, %1}, %2;" : "=f"(lo), "=f"(hi) : "l"(v));
}

// One (oh,cin,kh) stage for parity P, base-alignment parity E (= w2&1).
// xq[j] = xsu[al + j] with al = base0 - E (16B-aligned); xp[q] == xq[q+E].
template <int P, int E>
__device__ __forceinline__ void accum_stage(u64 acc[18],
                                            const u64* __restrict__ xsu,
                                            int oh, int kh, int cin,
                                            int w2, int lane) {
    constexpr int NW = P ? 2 : 3;         // kw = 2*kwi + P
    int ah = ((oh + 2 - kh) >> 1) + 1;    // in [0,4]

    const u64* wbase = g_wp + (cin * 5 + kh) * 800 + (P ? 480 : 0) + lane;
    u64 wreg[5][NW];
#pragma unroll
    for (int kd = 0; kd < 5; kd++)
#pragma unroll
        for (int kwi = 0; kwi < NW; kwi++)
            wreg[kd][kwi] = __ldg(wbase + (kd * NW + kwi) * 32);  // coalesced LDG.64

    // aligned x base for this stage (even u64 index -> 16B aligned)
    const ulonglong2* xb2 =
        (const ulonglong2*)(xsu + ((cin * 25 + ah) * 32 + 3 * w2 - E));
#pragma unroll
    for (int a = 0; a < 5; a++) {
        u64 xq[6];
        // need j range: [P+E, 4+E]; v0 (j=0,1) only needed when P+E<2
        if (P == 1 && E == 1) {
            ulonglong2 v1 = xb2[a * 80 + 1], v2 = xb2[a * 80 + 2];
            xq[2] = v1.x; xq[3] = v1.y; xq[4] = v2.x; xq[5] = v2.y;
        } else {
            ulonglong2 v0 = xb2[a * 80 + 0], v1 = xb2[a * 80 + 1], v2 = xb2[a * 80 + 2];
            xq[0] = v0.x; xq[1] = v0.y; xq[2] = v1.x; xq[3] = v1.y;
            xq[4] = v2.x; xq[5] = v2.y;
        }
#pragma unroll
        for (int kd = 0; kd < 5; kd++) {
            int odl = 2 * a + kd - 4;      // compile-time after unroll
            if (odl < 0 || odl > 5) continue;
#pragma unroll
            for (int kwi = 0; kwi < NW; kwi++) {
#pragma unroll
                for (int t3 = 0; t3 < 3; t3++) {   // ow = P + 2*t3
                    acc[odl * 3 + t3] =
                        ffma2(wreg[kd][kwi], xq[2 - kwi + t3 + E], acc[odl * 3 + t3]);
                }
            }
        }
    }
}

// Full conv + pooled max for this warp's (w2, P) slice.
template <int P, int E>
__device__ __forceinline__ void conv_all(const u64* __restrict__ xsu,
                                         int w2, int lane, float& m0, float& m1) {
#pragma unroll 1
    for (int oh = 0; oh < 6; oh++) {
        int par = oh & 1;
        u64 acc[18];
#pragma unroll
        for (int i = 0; i < 18; i++) acc[i] = 0ull;

#pragma unroll 1
        for (int cin = 0; cin < CIN; cin++) {
            if (par) {
#pragma unroll
                for (int khi = 0; khi < 2; khi++)
                    accum_stage<P, E>(acc, xsu, oh, 1 + 2 * khi, cin, w2, lane);
            } else {
#pragma unroll
                for (int khi = 0; khi < 3; khi++)
                    accum_stage<P, E>(acc, xsu, oh, 2 * khi, cin, w2, lane);
            }
        }

        // fold this oh-plane slice (6 od x 3 ow of this parity) into running max
#pragma unroll
        for (int i = 0; i < 18; i++) {
            float lo, hi;
            unpack2(acc[i], lo, hi);
            m0 = fmaxf(m0, lo);
            m1 = fmaxf(m1, hi);
        }
    }
}

extern __shared__ u64 smem_dyn[];

__global__ void __launch_bounds__(NTH, 1)
fused_kernel(const float* __restrict__ x, const float* __restrict__ bias,
             float* __restrict__ out) {
    u64* xsu = smem_dyn;                  // 25600 u64, duplicated f32x2

    int blk = blockIdx.x;
    int h2 = blk % 10;
    int d2 = (blk / 10) % 5;
    int n = blk / 50;
    int tid = threadIdx.x;

    // ---- load input patch: cin x (id0..id0+4) x (ih0..ih0+4) x (iw=-1..30) ----
    int id0 = 3 * d2 - 1, ih0 = 3 * h2 - 1;
    const float* xbase = x + (size_t)n * CIN * DI * HI * WI;
    for (int i = tid; i < XS_ELEMS; i += NTH) {
        int slot = i & 31;               // iw + 1
        int ah = (i >> 5) % 5;
        int rest = i / 160;
        int ad = rest % 5;
        int cin = rest / 5;
        int iw = slot - 1, id = id0 + ad, ih = ih0 + ah;
        float v = 0.f;
        if (iw >= 0 && id >= 0 && ih >= 0)   // upper bounds always in range for used windows
            v = xbase[((cin * DI + id) * HI + ih) * WI + iw];
        unsigned int u = __float_as_uint(v);
        xsu[i] = ((u64)u << 32) | (u64)u;    // duplicate into both f32x2 halves
    }
    __syncthreads();

    int wid = tid >> 5;
    int w2 = wid % 10;                   // output w2 window
    int p = wid / 10;                    // ow parity handled by this warp
    int lane = tid & 31;                 // cout pair (2*lane, 2*lane+1)
    float m0 = -3.4e38f, m1 = -3.4e38f;

    if (p == 0) {
        if (w2 & 1) conv_all<0, 1>(xsu, w2, lane, m0, m1);
        else        conv_all<0, 0>(xsu, w2, lane, m0, m1);
    } else {
        if (w2 & 1) conv_all<1, 1>(xsu, w2, lane, m0, m1);
        else        conv_all<1, 0>(xsu, w2, lane, m0, m1);
    }

    // ---- merge ow parities (x patch dead -> reuse smem), bias, channel sum ----
    __syncthreads();
    float* red = (float*)smem_dyn;
    if (p == 1) {
        red[(w2 * 32 + lane) * 2 + 0] = m0;
        red[(w2 * 32 + lane) * 2 + 1] = m1;
    }
    __syncthreads();
    if (p == 0) {
        m0 = fmaxf(m0, red[(w2 * 32 + lane) * 2 + 0]);
        m1 = fmaxf(m1, red[(w2 * 32 + lane) * 2 + 1]);
        float b0 = bias[2 * lane], b1 = bias[2 * lane + 1];
        float sm = (m0 + b0) + (m1 + b1);    // bias after max; sum lane's 2 couts
#pragma unroll
        for (int off = 16; off; off >>= 1) sm += __shfl_xor_sync(0xffffffffu, sm, off);
        if (lane == 0) out[((n * 5 + d2) * 10 + h2) * 10 + w2] = sm;
    }
}

extern "C" void kernel_launch(void* const* d_in, const int* in_sizes, int n_in,
                              void* d_out, int out_size) {
    const float* x = (const float*)d_in[0];
    const float* w = (const float*)d_in[1];
    const float* b = (const float*)d_in[2];
    float* out = (float*)d_out;

    static int configured = 0;
    if (!configured) {
        cudaFuncSetAttribute(fused_kernel, cudaFuncAttributeMaxDynamicSharedMemorySize,
                             SMEM_BYTES);
        configured = 1;
    }

    prep_kernel<<<(CIN * 5 * 800 + 255) / 256, 256>>>(w);
    fused_kernel<<<16 * 5 * 10, NTH, SMEM_BYTES>>>(x, b, out);
}

// round 16
// speedup vs baseline: 3.8920x; 2.9545x over previous
#include <cuda_runtime.h>
#include <cstdint>

// Fused ConvTranspose3d(32->64,k5,s2,p2) + MaxPool2 + MaxPool3 + channel-sum,
// rewritten as implicit GEMM on tensor cores (mma.sync m16n8k8 tf32).
//
// Pools compose to a 6x6x6 stride-6 max over conv output; bias folds after max.
// Parity: od==kd, oh==kh, ow==kw (mod 2) => 8 parity classes, each a dense GEMM
//   D[pos, cout] = sum_k A[pos, k] * W[k, cout],  K_class = 32*nd*nh*nw.
// CTA = (n,d2,h2): per class, per w2 window: 3x3x3 = 27 positions -> 2 m16 tiles.
// 640 threads = 20 warps = (w2 0..9) x (cout-half). Per warp: 8 classes x 2 mt x
// 4 ntiles x (K/8) ksteps of m16n8k8 MMAs = 4000 MMAs.
// x patch in smem as tf32-prerounded bits, [cin][25][33] (33-col pad vs conflicts).
// Weights pre-baked in exact B-fragment order (u64 per lane) by prep kernel.

#define CIN 32
#define COUT 64
#define DI 16
#define HI 32
#define WI 32
#define NTH 640
#define XS_U32 26400                    // 32 cin * 25 (ad*5+ah) * 33 cols
#define SMEM_BYTES (XS_U32 * 4)         // 105600 B

typedef unsigned int u32;
typedef unsigned long long u64;

// [ksg 0..499][ntile 0..7][lane 0..31] -> (b1<<32)|b0  (tf32 bits)
// b0 = W[k = ks*8 + lane%4,  cout = ntile*8 + lane/4],  b1 = same with k+4.
__device__ u64 g_wB[500 * 8 * 32];

__constant__ int kOfs[9] = {0, 108, 180, 252, 300, 372, 420, 468, 500};

__device__ __forceinline__ u32 tf32r(float f) {
    u32 r;
    asm("cvt.rna.tf32.f32 %0, %1;" : "=r"(r) : "f"(f));
    return r;
}

__global__ void prep_wB(const float* __restrict__ w) {
    int idx = blockIdx.x * blockDim.x + threadIdx.x;
    if (idx >= 500 * 8 * 32) return;
    int lane = idx & 31;
    int ntg = (idx >> 5) & 7;
    int ksg = idx >> 8;
    int cls = 0;
#pragma unroll
    for (int c = 1; c < 8; c++)
        if (ksg >= kOfs[c]) cls = c;
    int ks = ksg - kOfs[cls];
    int pd = (cls >> 2) & 1, ph = (cls >> 1) & 1, pw = cls & 1;
    int nh = 3 - ph, nw = 3 - pw;
    int tap = ks >> 2, cq = ks & 3;
    int kwi = tap % nw;
    int tmp = tap / nw;
    int khi = tmp % nh;
    int kdi = tmp / nh;
    int kd = pd + 2 * kdi, kh = ph + 2 * khi, kw = pw + 2 * kwi;
    int tapidx = (kd * 5 + kh) * 5 + kw;         // torch tap order
    int c4 = lane & 3, gg = lane >> 2;
    int cin = cq * 8 + c4;
    int cout = ntg * 8 + gg;
    u32 b0 = tf32r(w[(cin * COUT + cout) * 125 + tapidx]);
    u32 b1 = tf32r(w[((cin + 4) * COUT + cout) * 125 + tapidx]);
    g_wB[idx] = ((u64)b1 << 32) | (u64)b0;
}

__device__ __forceinline__ void mma8(float& d0, float& d1, float& d2, float& d3,
                                     u32 a0, u32 a1, u32 a2, u32 a3,
                                     u32 b0, u32 b1) {
    asm volatile(
        "mma.sync.aligned.m16n8k8.row.col.f32.tf32.tf32.f32 "
        "{%0,%1,%2,%3}, {%4,%5,%6,%7}, {%8,%9}, {%0,%1,%2,%3};"
        : "+f"(d0), "+f"(d1), "+f"(d2), "+f"(d3)
        : "r"(a0), "r"(a1), "r"(a2), "r"(a3), "r"(b0), "r"(b1));
}

extern __shared__ u32 xs[];   // tf32 bits of x patch, [cin][ad*5+ah][col]

__global__ void __launch_bounds__(NTH, 1)
fused_kernel(const float* __restrict__ x, const float* __restrict__ bias,
             float* __restrict__ out) {
    int blk = blockIdx.x;
    int h2 = blk % 10;
    int d2 = (blk / 10) % 5;
    int n = blk / 50;
    int tid = threadIdx.x;

    // ---- load x patch (tf32-rounded): cin x ad(0..4) x ah(0..4) x col(0..32) ----
    // col = iw + 1 for col<32 (iw -1..30); col 32 is pad.
    int id0 = 3 * d2 - 1, ih0 = 3 * h2 - 1;
    const float* xbase = x + (size_t)n * CIN * DI * HI * WI;
    for (int i = tid; i < XS_U32; i += NTH) {
        int col = i % 33;
        int rest = i / 33;
        int ah = rest % 5;
        int ad = (rest / 5) % 5;
        int cin = rest / 25;
        int iw = col - 1, id = id0 + ad, ih = ih0 + ah;
        float v = 0.f;
        if (col < 32 && iw >= 0 && id >= 0 && ih >= 0)   // upper bounds always ok
            v = xbase[((cin * DI + id) * HI + ih) * WI + iw];
        xs[i] = tf32r(v);
    }
    __syncthreads();

    int wid = tid >> 5;
    int w2 = wid % 10;                  // output w2 window
    int nhalf = wid / 10;               // cout half (ntiles nhalf*4 .. +3)
    int lane = tid & 31;
    int c4 = lane & 3;                  // threadID_in_group
    int g = lane >> 2;                  // groupID

    // per-thread m-rows (class-independent): r = 8*rr + g, tile1 second clamped
    // row r -> (odi,ohi,owi) = (r/9, (r%9)/3, r%3); rowbase in x patch:
    int rb[4];
#pragma unroll
    for (int rr = 0; rr < 4; rr++) {
        int r = rr * 8 + g;
        if (r > 26) r = 26;             // pad rows (excluded from max fold)
        int odi = r / 9;
        int rem = r - odi * 9;
        int ohi = rem / 3;
        int owi = rem - ohi * 3;
        rb[rr] = ((odi + 2) * 5 + (ohi + 2)) * 33 + 3 * w2 + owi + 2;
    }

    float mmax[8];                      // [ntile 0..3][cout j 0..1]
#pragma unroll
    for (int i = 0; i < 8; i++) mmax[i] = -3.4e38f;

    int ksg = 0;
#pragma unroll 1
    for (int cls = 0; cls < 8; cls++) {
        int nd = 3 - ((cls >> 2) & 1);
        int nh = 3 - ((cls >> 1) & 1);
        int nw = 3 - (cls & 1);

        float D[32];                    // [mt 0..1][ntile 0..3][frag 0..3]
#pragma unroll
        for (int i = 0; i < 32; i++) D[i] = 0.f;

#pragma unroll 1
        for (int kdi = 0; kdi < nd; kdi++) {
#pragma unroll 1
            for (int khi = 0; khi < nh; khi++) {
#pragma unroll 1
                for (int kwi = 0; kwi < nw; kwi++) {
                    int tofs = kdi * 165 + khi * 33 + kwi;
#pragma unroll
                    for (int cq = 0; cq < 4; cq++) {
                        int ab = (cq * 8 + c4) * 825 - tofs;
                        // A fragments (tf32 m16n8k8): a0(g,c) a1(g+8,c) a2(g,c+4) a3(g+8,c+4)
                        u32 a00 = xs[rb[0] + ab];
                        u32 a01 = xs[rb[1] + ab];
                        u32 a02 = xs[rb[0] + ab + 3300];   // cin + 4
                        u32 a03 = xs[rb[1] + ab + 3300];
                        u32 a10 = xs[rb[2] + ab];
                        u32 a11 = xs[rb[3] + ab];
                        u32 a12 = xs[rb[2] + ab + 3300];
                        u32 a13 = xs[rb[3] + ab + 3300];
                        const u64* bq = g_wB + ((size_t)ksg << 8) + (nhalf << 7) + lane;
#pragma unroll
                        for (int nt = 0; nt < 4; nt++) {
                            u64 bv = __ldg(bq + (nt << 5));
                            u32 b0 = (u32)bv, b1 = (u32)(bv >> 32);
                            mma8(D[nt * 4 + 0], D[nt * 4 + 1], D[nt * 4 + 2], D[nt * 4 + 3],
                                 a00, a01, a02, a03, b0, b1);
                            mma8(D[16 + nt * 4 + 0], D[16 + nt * 4 + 1],
                                 D[16 + nt * 4 + 2], D[16 + nt * 4 + 3],
                                 a10, a11, a12, a13, b0, b1);
                        }
                        ksg++;
                    }
                }
            }
        }

        // fold D into running max. D frag rows: d0,d1 -> row g (+16 for mt1);
        // d2,d3 -> row g+8 (+16). mt1 rows 24+g valid only for g<3.
        bool hi1 = (g < 3);
#pragma unroll
        for (int nt = 0; nt < 4; nt++) {
            mmax[nt * 2 + 0] = fmaxf(mmax[nt * 2 + 0],
                                     fmaxf(D[nt * 4 + 0], D[nt * 4 + 2]));
            mmax[nt * 2 + 1] = fmaxf(mmax[nt * 2 + 1],
                                     fmaxf(D[nt * 4 + 1], D[nt * 4 + 3]));
            mmax[nt * 2 + 0] = fmaxf(mmax[nt * 2 + 0], D[16 + nt * 4 + 0]);
            mmax[nt * 2 + 1] = fmaxf(mmax[nt * 2 + 1], D[16 + nt * 4 + 1]);
            if (hi1) {
                mmax[nt * 2 + 0] = fmaxf(mmax[nt * 2 + 0], D[16 + nt * 4 + 2]);
                mmax[nt * 2 + 1] = fmaxf(mmax[nt * 2 + 1], D[16 + nt * 4 + 3]);
            }
        }
    }

    // ---- reduce max over rows (threads differing in g), then bias + cout sum ----
#pragma unroll
    for (int i = 0; i < 8; i++) {
#pragma unroll
        for (int off = 4; off <= 16; off <<= 1)
            mmax[i] = fmaxf(mmax[i], __shfl_xor_sync(0xffffffffu, mmax[i], off));
    }
    float s = 0.f;
    if (g == 0) {
#pragma unroll
        for (int nt = 0; nt < 4; nt++)
#pragma unroll
            for (int j = 0; j < 2; j++) {
                int cout = nhalf * 32 + nt * 8 + 2 * c4 + j;
                s += mmax[nt * 2 + j] + bias[cout];
            }
    }
#pragma unroll
    for (int off = 16; off; off >>= 1) s += __shfl_xor_sync(0xffffffffu, s, off);

    __syncthreads();                    // x patch dead -> reuse smem
    float* red = (float*)xs;
    if (lane == 0) red[wid] = s;        // wid = nhalf*10 + w2
    __syncthreads();
    if (tid < 10)
        out[((n * 5 + d2) * 10 + h2) * 10 + tid] = red[tid] + red[tid + 10];
}

extern "C" void kernel_launch(void* const* d_in, const int* in_sizes, int n_in,
                              void* d_out, int out_size) {
    const float* x = (const float*)d_in[0];
    const float* w = (const float*)d_in[1];
    const float* b = (const float*)d_in[2];
    float* out = (float*)d_out;

    static int configured = 0;
    if (!configured) {
        cudaFuncSetAttribute(fused_kernel, cudaFuncAttributeMaxDynamicSharedMemorySize,
                             SMEM_BYTES);
        configured = 1;
    }

    prep_wB<<<(500 * 8 * 32 + 255) / 256, 256>>>(w);
    fused_kernel<<<16 * 5 * 10, NTH, SMEM_BYTES>>>(x, b, out);
}